// round 4
// baseline (speedup 1.0000x reference)
#include <cuda_runtime.h>

// Farthest point sampling + gather, bit-exact replication of the JAX reference.
// B=8 batches, N=131072 points, S=4096 samples.
//
// Persistent kernel: 16 CTAs per batch, software barrier per batch (all 128
// CTAs co-resident: 512 threads/CTA, 1 CTA/SM, 128 < 148 SMs).
// min_dist kept in registers (16 floats/thread). Coords in SoA device scratch
// for vectorized loads (L1-resident per-CTA slice).
//
// R3 change: distance = fma(dz,dz, fma(dx,dx, rn(dy*dy))).
// Derivation: XLA:GPU -> LLVM NVPTX with AllowFPOpFusion::Fast. The reduce
// chain ((0+dx^2)+dy^2)+dz^2 contracts as:
//   fadd(fmul(dx),fmul(dy)) -> fma(dx,dx, rn(dy*dy))   [operand-0 mul fused]
//   fadd(fma, fmul(dz))     -> fma(dz,dz, acc)
// so the PRE-ROUNDED square is dy^2 (R1 wrongly pre-rounded dx^2).

#define NB 8
#define NP 131072
#define NS 4096
#define CPB 16                 // CTAs per batch
#define NT 512                 // threads per CTA
#define ROUNDS (NS - 1)        // 4095 argmax rounds (selection 0 is index 0)
#define PPC (NP / CPB)         // 8192 points per CTA
#define CHUNK 4                // float4 chunks per thread per coord => 16 pts/thread

__device__ float    g_x[NB * NP];
__device__ float    g_y[NB * NP];
__device__ float    g_z[NB * NP];
__device__ unsigned g_cnt[NB];
__device__ float    g_pv[2][NB][CPB];
__device__ int      g_pi[2][NB][CPB];

__global__ void fps_init_kernel() {
    if (threadIdx.x < NB) g_cnt[threadIdx.x] = 0u;
}

__global__ void fps_soa_kernel(const float* __restrict__ pts) {
    int i = blockIdx.x * blockDim.x + threadIdx.x;
    int stride = gridDim.x * blockDim.x;
    for (; i < NB * NP; i += stride) {
        g_x[i] = pts[3 * i + 0];
        g_y[i] = pts[3 * i + 1];
        g_z[i] = pts[3 * i + 2];
    }
}

__global__ void __launch_bounds__(NT, 1) fps_main_kernel(float* __restrict__ out) {
    const int b    = blockIdx.x / CPB;
    const int c    = blockIdx.x % CPB;
    const int tid  = threadIdx.x;
    const int lane = tid & 31;
    const int wid  = tid >> 5;
    const int base = c * PPC;

    const float4* __restrict__ x4 = (const float4*)(g_x + b * NP + base);
    const float4* __restrict__ y4 = (const float4*)(g_y + b * NP + base);
    const float4* __restrict__ z4 = (const float4*)(g_z + b * NP + base);

    float md[CHUNK * 4];
#pragma unroll
    for (int i = 0; i < CHUNK * 4; ++i) md[i] = 1e10f;   // BIG

    __shared__ float s_v[NT / 32];
    __shared__ int   s_i[NT / 32];
    __shared__ float s_l[3];

    // selection 0 is always index 0 (scan emits initial last_idx first)
    float lx = g_x[b * NP + 0];
    float ly = g_y[b * NP + 0];
    float lz = g_z[b * NP + 0];

    if (c == 0 && tid == 0) {
        out[(b * NS + 0) * 3 + 0] = lx;
        out[(b * NS + 0) * 3 + 1] = ly;
        out[(b * NS + 0) * 3 + 2] = lz;
    }

    for (int r = 0; r < ROUNDS; ++r) {
        float bestv = -1.0f;   // min_dist >= 0 always
        int   besti = 0x7fffffff;

#pragma unroll
        for (int j = 0; j < CHUNK; ++j) {
            const int e = j * NT + tid;
            float4 X = x4[e];
            float4 Y = y4[e];
            float4 Z = z4[e];
            float xv[4] = {X.x, X.y, X.z, X.w};
            float yv[4] = {Y.x, Y.y, Y.z, Y.w};
            float zv[4] = {Z.x, Z.y, Z.z, Z.w};
            const int idx0 = base + e * 4;
#pragma unroll
            for (int k = 0; k < 4; ++k) {
                // XLA:GPU contraction: fma(dz,dz, fma(dx,dx, rn(dy*dy)))
                float dx = __fsub_rn(xv[k], lx);
                float dy = __fsub_rn(yv[k], ly);
                float dz = __fsub_rn(zv[k], lz);
                float d  = __fmaf_rn(dz, dz,
                           __fmaf_rn(dx, dx,
                           __fmul_rn(dy, dy)));
                float m  = fminf(md[j * 4 + k], d);
                md[j * 4 + k] = m;
                // ascending index order + strict '>' == first-occurrence argmax
                if (m > bestv) { bestv = m; besti = idx0 + k; }
            }
        }

        // warp argmax (tiebreak: smaller index)
#pragma unroll
        for (int off = 16; off > 0; off >>= 1) {
            float ov = __shfl_down_sync(0xffffffffu, bestv, off);
            int   oi = __shfl_down_sync(0xffffffffu, besti, off);
            if (ov > bestv || (ov == bestv && oi < besti)) { bestv = ov; besti = oi; }
        }
        if (lane == 0) { s_v[wid] = bestv; s_i[wid] = besti; }
        __syncthreads();

        if (wid == 0) {
            // CTA reduce of 16 warp results
            float v  = (lane < NT / 32) ? s_v[lane] : -2.0f;
            int   i2 = (lane < NT / 32) ? s_i[lane] : 0x7fffffff;
#pragma unroll
            for (int off = 8; off > 0; off >>= 1) {
                float ov = __shfl_down_sync(0xffffffffu, v, off);
                int   oi = __shfl_down_sync(0xffffffffu, i2, off);
                if (ov > v || (ov == v && oi < i2)) { v = ov; i2 = oi; }
            }
            // volatile: stores/loads bypass non-coherent L1, round-trip to L2
            volatile float* pv_slot = &g_pv[r & 1][b][0];
            volatile int*   pi_slot = &g_pi[r & 1][b][0];
            if (lane == 0) {
                pv_slot[c] = v;
                pi_slot[c] = i2;
                __threadfence();              // release partials to gpu scope
                atomicAdd(&g_cnt[b], 1u);     // arrive
            }
            // all 32 lanes of warp 0 spin (broadcast load) until all 16 CTAs arrived
            const unsigned tgt = (unsigned)(r + 1) * CPB;
            volatile unsigned* cp = (volatile unsigned*)&g_cnt[b];
            while (*cp < tgt) { }
            __threadfence();                  // acquire

            // cross-CTA reduce of 16 partials (redundant per CTA, no 2nd barrier;
            // partials are double-buffered by round parity)
            float pv = (lane < CPB) ? pv_slot[lane] : -2.0f;
            int   pi = (lane < CPB) ? pi_slot[lane] : 0x7fffffff;
#pragma unroll
            for (int off = 8; off > 0; off >>= 1) {
                float ov = __shfl_down_sync(0xffffffffu, pv, off);
                int   oi = __shfl_down_sync(0xffffffffu, pi, off);
                if (ov > pv || (ov == pv && oi < pi)) { pv = ov; pi = oi; }
            }
            if (lane == 0) {
                // g_x/y/z are immutable intra-launch: plain (L1) loads are safe
                float wx = g_x[b * NP + pi];
                float wy = g_y[b * NP + pi];
                float wz = g_z[b * NP + pi];
                s_l[0] = wx; s_l[1] = wy; s_l[2] = wz;
                if (c == 0) {   // batch leader writes the gathered output
                    out[(b * NS + r + 1) * 3 + 0] = wx;
                    out[(b * NS + r + 1) * 3 + 1] = wy;
                    out[(b * NS + r + 1) * 3 + 2] = wz;
                }
            }
        }
        __syncthreads();
        lx = s_l[0]; ly = s_l[1]; lz = s_l[2];
    }
}

extern "C" void kernel_launch(void* const* d_in, const int* in_sizes, int n_in,
                              void* d_out, int out_size) {
    const float* pts = (const float*)d_in[0];
    float* out = (float*)d_out;
    (void)in_sizes; (void)n_in; (void)out_size;

    fps_init_kernel<<<1, 32>>>();
    fps_soa_kernel<<<512, 256>>>(pts);
    fps_main_kernel<<<NB * CPB, NT>>>(out);
}